// round 16
// baseline (speedup 1.0000x reference)
#include <cuda_runtime.h>
#include <cuda_fp16.h>
#include <cstdint>
#include <cstddef>

#define BATCH 2048
#define DIN   512
#define HID   1024
#define NSTEPS 9
#define CLAMPV 100.0f

// ---------------- scratch (static __device__, no allocations) ----------------
__device__ __align__(16) float  g_Z[BATCH * DIN];
__device__ __align__(16) float  g_LL[BATCH];
__device__ __align__(16) __half g_ZIN[BATCH * DIN];
__device__ __align__(16) float  g_K[4][BATCH * DIN];
__device__ __align__(16) float  g_KD[4][BATCH];                 // raw div sums (atomic)
__device__ __align__(16) __half g_H[4][(size_t)BATCH * HID];    // per-stage H buffers
__device__ __align__(16) __half g_E[(size_t)2 * BATCH * DIN];
__device__ __align__(16) __half g_W1T[(size_t)HID * DIN];       // W1^T K-major
__device__ __align__(16) __half g_WIL[(size_t)2 * HID * DIN];   // interleaved [u_k;v_k] rows
__device__ __align__(16) __half g_W2T[(size_t)DIN * HID];       // W2^T K-major

// ---------------- threefry2x32 (exact JAX implementation) ----------------
__host__ __device__ inline uint32_t rotl32(uint32_t x, int d) {
    return (x << d) | (x >> (32 - d));
}
__host__ __device__ inline void tfry(uint32_t k0, uint32_t k1,
                                     uint32_t c0, uint32_t c1,
                                     uint32_t& o0, uint32_t& o1) {
    uint32_t ks0 = k0, ks1 = k1, ks2 = k0 ^ k1 ^ 0x1BD11BDAu;
    uint32_t x0 = c0 + ks0, x1 = c1 + ks1;
#define TF_ROUND(rot) { x0 += x1; x1 = rotl32(x1, rot) ^ x0; }
    TF_ROUND(13) TF_ROUND(15) TF_ROUND(26) TF_ROUND(6)
    x0 += ks1; x1 += ks2 + 1u;
    TF_ROUND(17) TF_ROUND(29) TF_ROUND(16) TF_ROUND(24)
    x0 += ks2; x1 += ks0 + 2u;
    TF_ROUND(13) TF_ROUND(15) TF_ROUND(26) TF_ROUND(6)
    x0 += ks0; x1 += ks1 + 3u;
    TF_ROUND(17) TF_ROUND(29) TF_ROUND(16) TF_ROUND(24)
    x0 += ks1; x1 += ks2 + 4u;
    TF_ROUND(13) TF_ROUND(15) TF_ROUND(26) TF_ROUND(6)
    x0 += ks2; x1 += ks0 + 5u;
#undef TF_ROUND
    o0 = x0; o1 = x1;
}

// ---------------- helpers ----------------
#define MMA_F16(d, a, b)                                                                \
    asm volatile(                                                                       \
        "mma.sync.aligned.m16n8k16.row.col.f32.f16.f16.f32 "                            \
        "{%0,%1,%2,%3}, {%4,%5,%6,%7}, {%8,%9}, {%0,%1,%2,%3};\n"                       \
        : "+f"((d)[0]), "+f"((d)[1]), "+f"((d)[2]), "+f"((d)[3])                        \
        : "r"((a)[0]), "r"((a)[1]), "r"((a)[2]), "r"((a)[3]), "r"((b)[0]), "r"((b)[1]))

#define LDMX4(r0, r1, r2, r3, addr)                                                     \
    asm volatile("ldmatrix.sync.aligned.m8n8.x4.shared.b16 {%0,%1,%2,%3}, [%4];"        \
                 : "=r"(r0), "=r"(r1), "=r"(r2), "=r"(r3) : "r"(addr))

#define CP16(dst, src) \
    asm volatile("cp.async.cg.shared.global [%0], [%1], 16;" :: "r"(dst), "l"(src) : "memory")
#define CP_COMMIT() asm volatile("cp.async.commit_group;" ::: "memory")
#define CP_WAIT1()  asm volatile("cp.async.wait_group 1;" ::: "memory")

__device__ inline float blockReduceSum(float v) {
    __shared__ float ws[8];
    int lane = threadIdx.x & 31, w = threadIdx.x >> 5;
#pragma unroll
    for (int o = 16; o > 0; o >>= 1) v += __shfl_down_sync(0xffffffffu, v, o);
    if (lane == 0) ws[w] = v;
    __syncthreads();
    if (w == 0) {
        v = (lane < ((int)blockDim.x >> 5)) ? ws[lane] : 0.f;
#pragma unroll
        for (int o = 4; o > 0; o >>= 1) v += __shfl_down_sync(0xffffffffu, v, o);
    }
    return v;
}

// ---------------- elementwise kernels ----------------
__global__ void init_kernel(const float* __restrict__ x) {
    int i = blockIdx.x * blockDim.x + threadIdx.x;
    if (i < BATCH * DIN) { float v = x[i]; g_Z[i] = v; g_ZIN[i] = __float2half_rn(v); }
    if (i < BATCH) g_LL[i] = 0.f;
}

__global__ void build_w1t(const float* __restrict__ W1) {
    int i = blockIdx.x * blockDim.x + threadIdx.x;
    if (i >= HID * DIN) return;
    int n = i / DIN, k = i % DIN;
    g_W1T[i] = __float2half_rn(W1[(size_t)k * HID + n]);
}
// interleaved: row 2k = W1[:,k] (u), row 2k+1 = W2[k,:] (v)
__global__ void build_wil(const float* __restrict__ W1, const float* __restrict__ W2) {
    int i = blockIdx.x * blockDim.x + threadIdx.x;
    if (i >= 2 * HID * DIN) return;
    int n = i / DIN, d = i % DIN;
    int k = n >> 1;
    float v = (n & 1) ? W2[(size_t)k * DIN + d] : W1[(size_t)d * HID + k];
    g_WIL[i] = __float2half_rn(v);
}
__global__ void build_w2t(const float* __restrict__ W2) {
    int i = blockIdx.x * blockDim.x + threadIdx.x;
    if (i >= DIN * HID) return;
    int n = i / HID, k = i % HID;
    g_W2T[i] = __float2half_rn(W2[(size_t)k * DIN + n]);
}

// ZIN = fp16_round(Z + c1 K0 + c2 K1 + c3 K2)   (stages 1..3 only)
__global__ void zin_kernel(float c1, float c2, float c3) {
    int i = blockIdx.x * blockDim.x + threadIdx.x;
    if (i >= BATCH * DIN) return;
    float v = g_Z[i] + c1 * g_K[0][i] + c2 * g_K[1][i] + c3 * g_K[2][i];
    g_ZIN[i] = __float2half_rn(v);
}

// Z update + ZIN refresh (main stream; reads only K)
__global__ void update_z(float dt8) {
    int i = blockIdx.x * blockDim.x + threadIdx.x;
    if (i >= BATCH * DIN) return;
    float z = g_Z[i] + dt8 * (g_K[0][i] + 3.f * (g_K[1][i] + g_K[2][i]) + g_K[3][i]);
    g_Z[i] = z;
    g_ZIN[i] = __float2half_rn(z);
}

// LL update (side stream; reads only KD — zeroing done by next step's gen_e)
__global__ void update_ll(float dt8) {
    int b = blockIdx.x * blockDim.x + threadIdx.x;
    if (b >= BATCH) return;
    float d[4];
#pragma unroll
    for (int s = 0; s < 4; s++) {
        float v = 0.5f * g_KD[s][b];
        d[s] = fminf(fmaxf(v, -CLAMPV), CLAMPV);
    }
    g_LL[b] += dt8 * (-d[0] - 3.f * (d[1] + d[2]) - d[3]);
}

// e gen + zero this stage's KD accumulator
__global__ void gen_e_kernel(uint32_t k0a, uint32_t k1a, uint32_t k0b, uint32_t k1b,
                             float* __restrict__ kdraw) {
    int i = blockIdx.x * blockDim.x + threadIdx.x;
    if (i >= BATCH * DIN) return;
    uint32_t k0 = blockIdx.y ? k0b : k0a;
    uint32_t k1 = blockIdx.y ? k1b : k1a;
    uint32_t o0, o1;
    tfry(k0, k1, 0u, (uint32_t)i, o0, o1);
    g_E[(size_t)blockIdx.y * BATCH * DIN + i] =
        ((o0 ^ o1) & 1u) ? __float2half_rn(1.f) : __float2half_rn(-1.f);
    if (blockIdx.y == 0 && i < BATCH) kdraw[i] = 0.f;
}

__global__ void finalize_kernel(float* __restrict__ out) {
    int b = blockIdx.x;
    float ssum = 0.f;
    for (int d = threadIdx.x; d < DIN; d += blockDim.x) {
        float v = g_Z[(size_t)b * DIN + d];
        out[(size_t)b * DIN + d] = v;
        ssum += v * v;
    }
    float tot = blockReduceSum(ssum);
    if (threadIdx.x == 0) out[(size_t)BATCH * DIN + b] = -0.5f * tot + g_LL[b];
}

// ---------------- fp16 mma.sync GEMM, cp.async 3-stage pipeline ----------------
// C[M,N] = A[M,K] @ Brows[N,K]^T, fp16 operands, fp32 accumulate.
// MODE 1: H[half] = fp16(tanh(acc+bias+tval*tvec))   MODE 2: C[float] = acc+bias
// MODE 3: no store; B cols (u,v)-interleaved; kdraw[b] += sum_k (1-h^2) u v
template <int BM, int BN, int MODE>
__global__ __launch_bounds__((BM / 32) * (BN / 32) * 32, 512 / ((BM / 32) * (BN / 32) * 32))
void gemm_mma(const __half* __restrict__ A, const __half* __restrict__ B,
              void* __restrict__ Cv, int M, int N, int K,
              const void* __restrict__ biasv, void* __restrict__ auxv, float tval) {
    extern __shared__ __align__(16) char smem[];
    constexpr int THREADS = (BM / 32) * (BN / 32) * 32;
    constexpr int WCOLS = BN / 32;
    constexpr int A16 = BM * 8 / THREADS;
    constexpr int B16 = BN * 8 / THREADS;
    constexpr int ABYTES = BM * 128;
    constexpr int BBYTES = BN * 128;

    float* sbias = (float*)smem;
    const uint32_t sA_u = (uint32_t)__cvta_generic_to_shared(smem + 1024);
    const uint32_t sB_u = sA_u + 3 * ABYTES;

    const int tid = threadIdx.x;
    const int lane = tid & 31;
    const int warp = tid >> 5;
    const int g = lane >> 2;
    const int tg = lane & 3;
    const int wrow = (warp / WCOLS) * 32;
    const int wcol = (warp % WCOLS) * 32;
    const int brow = blockIdx.y * BM;
    const int bcol = blockIdx.x * BN;

    if (MODE == 1 && tid < BN) {
        const float* bias = (const float*)biasv;
        const float* tvec = (const float*)auxv;
        sbias[tid] = bias[bcol + tid] + tval * tvec[bcol + tid];
    }
    if (MODE == 2 && tid < BN) sbias[tid] = ((const float*)biasv)[bcol + tid];

    float acc[2][4][4];
#pragma unroll
    for (int i = 0; i < 2; i++)
#pragma unroll
        for (int j = 0; j < 4; j++)
#pragma unroll
            for (int q = 0; q < 4; q++) acc[i][j][q] = 0.f;

    const int rA_l = wrow + (lane & 15);
    const int cA_l = lane >> 4;
    const int rB_l = wcol + ((lane >> 4) * 8) + (lane & 7);
    const int cB_l = (lane >> 3) & 1;

    const int nk = K >> 6;   // 64 halves per k-tile

#define ISSUE_COPY(st, kt)                                                              \
    do {                                                                                \
        _Pragma("unroll")                                                               \
        for (int i = 0; i < A16; i++) {                                                 \
            int f = tid + i * THREADS; int r = f >> 3, seg = f & 7;                     \
            uint32_t dst = sA_u + (st) * ABYTES + r * 128 + ((seg * 16) ^ ((r & 7) * 16)); \
            CP16(dst, A + (size_t)(brow + r) * K + (kt) + seg * 8);                     \
        }                                                                               \
        _Pragma("unroll")                                                               \
        for (int i = 0; i < B16; i++) {                                                 \
            int f = tid + i * THREADS; int r = f >> 3, seg = f & 7;                     \
            uint32_t dst = sB_u + (st) * BBYTES + r * 128 + ((seg * 16) ^ ((r & 7) * 16)); \
            CP16(dst, B + (size_t)(bcol + r) * K + (kt) + seg * 8);                     \
        }                                                                               \
    } while (0)

    ISSUE_COPY(0, 0);
    CP_COMMIT();
    if (1 < nk) ISSUE_COPY(1, 64);
    CP_COMMIT();

    int t_issue = 2;
    for (int t = 0; t < nk; t++) {
        CP_WAIT1();
        __syncthreads();
        if (t_issue < nk) {
            int st = t_issue - (t_issue / 3) * 3;
            ISSUE_COPY(st, t_issue << 6);
        }
        CP_COMMIT();
        t_issue++;

        const int slot = t - (t / 3) * 3;
        const uint32_t sa = sA_u + slot * ABYTES;
        const uint32_t sb = sB_u + slot * BBYTES;
#pragma unroll
        for (int ks = 0; ks < 4; ks++) {
            uint32_t af[2][4], bf[4][2];
#pragma unroll
            for (int mt = 0; mt < 2; mt++) {
                int r = rA_l + mt * 16;
                int ch = ks * 2 + cA_l;
                uint32_t addr = sa + r * 128 + ((ch * 16) ^ ((r & 7) * 16));
                LDMX4(af[mt][0], af[mt][1], af[mt][2], af[mt][3], addr);
            }
#pragma unroll
            for (int p = 0; p < 2; p++) {
                int r = rB_l + p * 16;
                int ch = ks * 2 + cB_l;
                uint32_t addr = sb + r * 128 + ((ch * 16) ^ ((r & 7) * 16));
                LDMX4(bf[2 * p][0], bf[2 * p][1], bf[2 * p + 1][0], bf[2 * p + 1][1], addr);
            }
#pragma unroll
            for (int mt = 0; mt < 2; mt++)
#pragma unroll
                for (int nt = 0; nt < 4; nt++)
                    MMA_F16(acc[mt][nt], af[mt], bf[nt]);
        }
    }
#undef ISSUE_COPY

    if (MODE == 3) {
        const __half* hmat = (const __half*)biasv;   // H matrix [BATCH, HID], fp16
        float* kdraw = (float*)auxv;                 // [BATCH]
        const int kbase = ((bcol + wcol) >> 1) + tg;
#pragma unroll
        for (int mt = 0; mt < 2; mt++) {
            int r0 = brow + wrow + mt * 16 + g;
            int b0 = r0 & (BATCH - 1);
            int b1 = (r0 + 8) & (BATCH - 1);
            float s0 = 0.f, s1 = 0.f;
#pragma unroll
            for (int nt = 0; nt < 4; nt++) {
                int kk = kbase + nt * 4;
                float h0 = __half2float(hmat[(size_t)b0 * HID + kk]);
                float h1 = __half2float(hmat[(size_t)b1 * HID + kk]);
                s0 += (1.f - h0 * h0) * acc[mt][nt][0] * acc[mt][nt][1];
                s1 += (1.f - h1 * h1) * acc[mt][nt][2] * acc[mt][nt][3];
            }
            s0 += __shfl_xor_sync(0xffffffffu, s0, 1);
            s0 += __shfl_xor_sync(0xffffffffu, s0, 2);
            s1 += __shfl_xor_sync(0xffffffffu, s1, 1);
            s1 += __shfl_xor_sync(0xffffffffu, s1, 2);
            if (tg == 0) {
                atomicAdd(&kdraw[b0], s0);
                atomicAdd(&kdraw[b1], s1);
            }
        }
        return;
    }

#pragma unroll
    for (int mt = 0; mt < 2; mt++) {
#pragma unroll
        for (int nt = 0; nt < 4; nt++) {
            int lc = wcol + nt * 8 + tg * 2;
            int r0 = brow + wrow + mt * 16 + g;
            float v0 = acc[mt][nt][0], v1 = acc[mt][nt][1];
            float v2 = acc[mt][nt][2], v3 = acc[mt][nt][3];
            if (MODE == 1) {
                __half* C = (__half*)Cv;
                float b0 = sbias[lc], b1 = sbias[lc + 1];
                __half2 h01 = __floats2half2_rn(tanhf(v0 + b0), tanhf(v1 + b1));
                __half2 h23 = __floats2half2_rn(tanhf(v2 + b0), tanhf(v3 + b1));
                *(__half2*)(C + (size_t)r0 * N + bcol + lc)       = h01;
                *(__half2*)(C + (size_t)(r0 + 8) * N + bcol + lc) = h23;
            } else {  // MODE 2
                float* C = (float*)Cv;
                float b0 = sbias[lc], b1 = sbias[lc + 1];
                v0 += b0; v1 += b1; v2 += b0; v3 += b1;
                *(float2*)(C + (size_t)r0 * N + bcol + lc)       = make_float2(v0, v1);
                *(float2*)(C + (size_t)(r0 + 8) * N + bcol + lc) = make_float2(v2, v3);
            }
        }
    }
}

// ---------------- host orchestration ----------------
extern "C" void kernel_launch(void* const* d_in, const int* in_sizes, int n_in,
                              void* d_out, int out_size) {
    (void)in_sizes; (void)n_in; (void)out_size;
    const float* x   = (const float*)d_in[0];
    const float* W1  = (const float*)d_in[1];
    const float* b1  = (const float*)d_in[2];
    const float* tw1 = (const float*)d_in[3];
    const float* W2  = (const float*)d_in[4];
    const float* b2  = (const float*)d_in[5];
    float* out = (float*)d_out;

    __half *pZIN, *pH, *pE, *pW1T, *pWIL, *pW2T;
    float *pK, *pKD;
    cudaGetSymbolAddress((void**)&pZIN, g_ZIN);
    cudaGetSymbolAddress((void**)&pH, g_H);
    cudaGetSymbolAddress((void**)&pE, g_E);
    cudaGetSymbolAddress((void**)&pW1T, g_W1T);
    cudaGetSymbolAddress((void**)&pWIL, g_WIL);
    cudaGetSymbolAddress((void**)&pW2T, g_W2T);
    cudaGetSymbolAddress((void**)&pK, g_K);
    cudaGetSymbolAddress((void**)&pKD, g_KD);

    // streams with priorities + fork-join events (created once; host resources only)
    static cudaStream_t sM = nullptr, sS = nullptr;
    static cudaEvent_t evRoot = nullptr, evG1 = nullptr, evS0 = nullptr,
                       evEndM = nullptr, evEndS = nullptr;
    if (!sM) {
        int loPri, hiPri;
        cudaDeviceGetStreamPriorityRange(&loPri, &hiPri);
        cudaStreamCreateWithPriority(&sM, cudaStreamNonBlocking, hiPri);  // main: high
        cudaStreamCreateWithPriority(&sS, cudaStreamNonBlocking, loPri);  // trace: low
        cudaEventCreateWithFlags(&evRoot, cudaEventDisableTiming);
        cudaEventCreateWithFlags(&evG1, cudaEventDisableTiming);
        cudaEventCreateWithFlags(&evS0, cudaEventDisableTiming);
        cudaEventCreateWithFlags(&evEndM, cudaEventDisableTiming);
        cudaEventCreateWithFlags(&evEndS, cudaEventDisableTiming);
    }

    const int SM_BIG = 1024 + 3 * (128 + 64) * 128;  // 74752
    const int SM_G2  = 1024 + 3 * (64 + 64) * 128;   // 50176
    cudaFuncSetAttribute((const void*)gemm_mma<128, 64, 1>,
                         cudaFuncAttributeMaxDynamicSharedMemorySize, SM_BIG);
    cudaFuncSetAttribute((const void*)gemm_mma<64, 64, 2>,
                         cudaFuncAttributeMaxDynamicSharedMemorySize, SM_G2);
    cudaFuncSetAttribute((const void*)gemm_mma<128, 64, 3>,
                         cudaFuncAttributeMaxDynamicSharedMemorySize, SM_BIG);

    // setup on the capture stream, then fork both worker streams
    init_kernel<<<(BATCH * DIN + 255) / 256, 256>>>(x);
    build_w1t<<<(HID * DIN + 255) / 256, 256>>>(W1);
    build_wil<<<(2 * HID * DIN + 255) / 256, 256>>>(W1, W2);
    build_w2t<<<(DIN * HID + 255) / 256, 256>>>(W2);
    cudaEventRecord(evRoot, 0);
    cudaStreamWaitEvent(sM, evRoot, 0);
    cudaStreamWaitEvent(sS, evRoot, 0);

    // JAX threefry, partitionable semantics
    uint32_t key0 = 0u, key1 = 1234u;

    for (int step = 0; step < NSTEPS; step++) {
        uint32_t nk0, nk1;
        uint32_t sk[4][2];
        tfry(key0, key1, 0u, 0u, nk0, nk1);
        for (int s = 0; s < 4; s++)
            tfry(key0, key1, 0u, (uint32_t)(s + 1), sk[s][0], sk[s][1]);
        key0 = nk0; key1 = nk1;

        double t0d = (double)step / 9.0, t1d = (double)(step + 1) / 9.0;
        float t0 = (float)t0d;
        float dt = (float)(t1d - t0d);
        float ts[4] = {t0, t0 + dt / 3.f, t0 + 2.f * dt / 3.f, (float)t1d};

        for (int s = 0; s < 4; s++) {
            __half* Hs = pH + (size_t)s * BATCH * HID;

            // ---- main stream (high priority): integrator chain ----
            if (s == 1)      zin_kernel<<<(BATCH * DIN + 255) / 256, 256, 0, sM>>>(dt / 3.f, 0.f, 0.f);
            else if (s == 2) zin_kernel<<<(BATCH * DIN + 255) / 256, 256, 0, sM>>>(-dt / 3.f, dt, 0.f);
            else if (s == 3) zin_kernel<<<(BATCH * DIN + 255) / 256, 256, 0, sM>>>(dt, -dt, dt);
            // (s == 0: ZIN already holds fp16(Z))

            // H-reuse guard: before overwriting H[0] for this step, ensure the
            // previous step's G3(0) (4 stages back) has drained the side stream
            if (s == 0 && step > 0) cudaStreamWaitEvent(sM, evS0, 0);

            // H[s] = fp16(tanh(zin @ W1 + b1 + t*tw1))   [2048x1024, K=512]
            gemm_mma<128, 64, 1><<<dim3(HID / 64, BATCH / 128), 256, SM_BIG, sM>>>(
                pZIN, pW1T, Hs, BATCH, HID, DIN, b1, (void*)tw1, ts[s]);
            cudaEventRecord(evG1, sM);
            // K[s] = H[s] @ W2 + b2                      [2048x512, K=1024]
            gemm_mma<64, 64, 2><<<dim3(DIN / 64, BATCH / 64), 128, SM_G2, sM>>>(
                Hs, pW2T, pK + (size_t)s * BATCH * DIN, BATCH, DIN, HID, b2, nullptr, 0.f);

            // ---- side stream (low priority): trace chain ----
            uint32_t keys_e[2][2];
            for (int i = 0; i < 2; i++) {
                uint32_t f0, f1;
                tfry(sk[s][0], sk[s][1], 0u, (uint32_t)i, f0, f1);
                tfry(f0, f1, 0u, 1u, keys_e[i][0], keys_e[i][1]);
            }
            gen_e_kernel<<<dim3(BATCH * DIN / 256, 2), 256, 0, sS>>>(
                keys_e[0][0], keys_e[0][1], keys_e[1][0], keys_e[1][1],
                pKD + (size_t)s * BATCH);
            cudaStreamWaitEvent(sS, evG1, 0);
            gemm_mma<128, 64, 3><<<dim3(2 * HID / 64, 2 * BATCH / 128), 256, SM_BIG, sS>>>(
                pE, pWIL, nullptr, 2 * BATCH, 2 * HID, DIN,
                Hs, pKD + (size_t)s * BATCH, 0.f);
            if (s == 0) cudaEventRecord(evS0, sS);
        }
        // main: z update (reads only K)
        update_z<<<(BATCH * DIN + 255) / 256, 256, 0, sM>>>(dt * 0.125f);
        // side: LL update (reads only KD); next step's gen_e re-zeroes after
        update_ll<<<(BATCH + 255) / 256, 256, 0, sS>>>(dt * 0.125f);
    }
    // single final join back into the capture stream
    cudaEventRecord(evEndM, sM);
    cudaEventRecord(evEndS, sS);
    cudaStreamWaitEvent(0, evEndM, 0);
    cudaStreamWaitEvent(0, evEndS, 0);
    finalize_kernel<<<BATCH, 256>>>(out);
}

// round 17
// speedup vs baseline: 1.0512x; 1.0512x over previous
#include <cuda_runtime.h>
#include <cuda_fp16.h>
#include <cstdint>
#include <cstddef>

#define BATCH 2048
#define DIN   512
#define HID   1024
#define NSTEPS 9
#define CLAMPV 100.0f

// ---------------- scratch (static __device__, no allocations) ----------------
__device__ __align__(16) float  g_Z[BATCH * DIN];
__device__ __align__(16) float  g_LL[BATCH];
__device__ __align__(16) __half g_ZIN[BATCH * DIN];
__device__ __align__(16) float  g_K[4][BATCH * DIN];
__device__ __align__(16) float  g_KD[4][BATCH];                 // raw div sums (atomic)
__device__ __align__(16) __half g_H[4][(size_t)BATCH * HID];    // per-stage H buffers
__device__ __align__(16) __half g_E[(size_t)2 * BATCH * DIN];
__device__ __align__(16) __half g_W1T[(size_t)HID * DIN];       // W1^T K-major
__device__ __align__(16) __half g_WIL[(size_t)2 * HID * DIN];   // interleaved [u_k;v_k] rows
__device__ __align__(16) __half g_W2T[(size_t)DIN * HID];       // W2^T K-major

// ---------------- threefry2x32 (exact JAX implementation) ----------------
__host__ __device__ inline uint32_t rotl32(uint32_t x, int d) {
    return (x << d) | (x >> (32 - d));
}
__host__ __device__ inline void tfry(uint32_t k0, uint32_t k1,
                                     uint32_t c0, uint32_t c1,
                                     uint32_t& o0, uint32_t& o1) {
    uint32_t ks0 = k0, ks1 = k1, ks2 = k0 ^ k1 ^ 0x1BD11BDAu;
    uint32_t x0 = c0 + ks0, x1 = c1 + ks1;
#define TF_ROUND(rot) { x0 += x1; x1 = rotl32(x1, rot) ^ x0; }
    TF_ROUND(13) TF_ROUND(15) TF_ROUND(26) TF_ROUND(6)
    x0 += ks1; x1 += ks2 + 1u;
    TF_ROUND(17) TF_ROUND(29) TF_ROUND(16) TF_ROUND(24)
    x0 += ks2; x1 += ks0 + 2u;
    TF_ROUND(13) TF_ROUND(15) TF_ROUND(26) TF_ROUND(6)
    x0 += ks0; x1 += ks1 + 3u;
    TF_ROUND(17) TF_ROUND(29) TF_ROUND(16) TF_ROUND(24)
    x0 += ks1; x1 += ks2 + 4u;
    TF_ROUND(13) TF_ROUND(15) TF_ROUND(26) TF_ROUND(6)
    x0 += ks2; x1 += ks0 + 5u;
#undef TF_ROUND
    o0 = x0; o1 = x1;
}

// ---------------- helpers ----------------
#define MMA_F16(d, a, b)                                                                \
    asm volatile(                                                                       \
        "mma.sync.aligned.m16n8k16.row.col.f32.f16.f16.f32 "                            \
        "{%0,%1,%2,%3}, {%4,%5,%6,%7}, {%8,%9}, {%0,%1,%2,%3};\n"                       \
        : "+f"((d)[0]), "+f"((d)[1]), "+f"((d)[2]), "+f"((d)[3])                        \
        : "r"((a)[0]), "r"((a)[1]), "r"((a)[2]), "r"((a)[3]), "r"((b)[0]), "r"((b)[1]))

#define LDMX4(r0, r1, r2, r3, addr)                                                     \
    asm volatile("ldmatrix.sync.aligned.m8n8.x4.shared.b16 {%0,%1,%2,%3}, [%4];"        \
                 : "=r"(r0), "=r"(r1), "=r"(r2), "=r"(r3) : "r"(addr))

#define CP16(dst, src) \
    asm volatile("cp.async.cg.shared.global [%0], [%1], 16;" :: "r"(dst), "l"(src) : "memory")
#define CP_COMMIT() asm volatile("cp.async.commit_group;" ::: "memory")
#define CP_WAIT1()  asm volatile("cp.async.wait_group 1;" ::: "memory")

__device__ inline float blockReduceSum(float v) {
    __shared__ float ws[8];
    int lane = threadIdx.x & 31, w = threadIdx.x >> 5;
#pragma unroll
    for (int o = 16; o > 0; o >>= 1) v += __shfl_down_sync(0xffffffffu, v, o);
    if (lane == 0) ws[w] = v;
    __syncthreads();
    if (w == 0) {
        v = (lane < ((int)blockDim.x >> 5)) ? ws[lane] : 0.f;
#pragma unroll
        for (int o = 4; o > 0; o >>= 1) v += __shfl_down_sync(0xffffffffu, v, o);
    }
    return v;
}

// ---------------- elementwise kernels ----------------
__global__ void init_kernel(const float* __restrict__ x) {
    int i = blockIdx.x * blockDim.x + threadIdx.x;
    if (i < BATCH * DIN) { float v = x[i]; g_Z[i] = v; g_ZIN[i] = __float2half_rn(v); }
    if (i < BATCH) g_LL[i] = 0.f;
}

__global__ void build_w1t(const float* __restrict__ W1) {
    int i = blockIdx.x * blockDim.x + threadIdx.x;
    if (i >= HID * DIN) return;
    int n = i / DIN, k = i % DIN;
    g_W1T[i] = __float2half_rn(W1[(size_t)k * HID + n]);
}
// interleaved: row 2k = W1[:,k] (u), row 2k+1 = W2[k,:] (v)
__global__ void build_wil(const float* __restrict__ W1, const float* __restrict__ W2) {
    int i = blockIdx.x * blockDim.x + threadIdx.x;
    if (i >= 2 * HID * DIN) return;
    int n = i / DIN, d = i % DIN;
    int k = n >> 1;
    float v = (n & 1) ? W2[(size_t)k * DIN + d] : W1[(size_t)d * HID + k];
    g_WIL[i] = __float2half_rn(v);
}
__global__ void build_w2t(const float* __restrict__ W2) {
    int i = blockIdx.x * blockDim.x + threadIdx.x;
    if (i >= DIN * HID) return;
    int n = i / HID, k = i % HID;
    g_W2T[i] = __float2half_rn(W2[(size_t)k * DIN + n]);
}

// ZIN = fp16_round(Z + c1 K0 + c2 K1 + c3 K2)   (stages 1..3 only)
__global__ void zin_kernel(float c1, float c2, float c3) {
    int i = blockIdx.x * blockDim.x + threadIdx.x;
    if (i >= BATCH * DIN) return;
    float v = g_Z[i] + c1 * g_K[0][i] + c2 * g_K[1][i] + c3 * g_K[2][i];
    g_ZIN[i] = __float2half_rn(v);
}

// Z update + ZIN refresh (main stream; reads only K)
__global__ void update_z(float dt8) {
    int i = blockIdx.x * blockDim.x + threadIdx.x;
    if (i >= BATCH * DIN) return;
    float z = g_Z[i] + dt8 * (g_K[0][i] + 3.f * (g_K[1][i] + g_K[2][i]) + g_K[3][i]);
    g_Z[i] = z;
    g_ZIN[i] = __float2half_rn(z);
}

// LL update (side stream; reads only KD — zeroing done by next step's gen_e)
__global__ void update_ll(float dt8) {
    int b = blockIdx.x * blockDim.x + threadIdx.x;
    if (b >= BATCH) return;
    float d[4];
#pragma unroll
    for (int s = 0; s < 4; s++) {
        float v = 0.5f * g_KD[s][b];
        d[s] = fminf(fmaxf(v, -CLAMPV), CLAMPV);
    }
    g_LL[b] += dt8 * (-d[0] - 3.f * (d[1] + d[2]) - d[3]);
}

// e gen + zero this stage's KD accumulator
__global__ void gen_e_kernel(uint32_t k0a, uint32_t k1a, uint32_t k0b, uint32_t k1b,
                             float* __restrict__ kdraw) {
    int i = blockIdx.x * blockDim.x + threadIdx.x;
    if (i >= BATCH * DIN) return;
    uint32_t k0 = blockIdx.y ? k0b : k0a;
    uint32_t k1 = blockIdx.y ? k1b : k1a;
    uint32_t o0, o1;
    tfry(k0, k1, 0u, (uint32_t)i, o0, o1);
    g_E[(size_t)blockIdx.y * BATCH * DIN + i] =
        ((o0 ^ o1) & 1u) ? __float2half_rn(1.f) : __float2half_rn(-1.f);
    if (blockIdx.y == 0 && i < BATCH) kdraw[i] = 0.f;
}

__global__ void finalize_kernel(float* __restrict__ out) {
    int b = blockIdx.x;
    float ssum = 0.f;
    for (int d = threadIdx.x; d < DIN; d += blockDim.x) {
        float v = g_Z[(size_t)b * DIN + d];
        out[(size_t)b * DIN + d] = v;
        ssum += v * v;
    }
    float tot = blockReduceSum(ssum);
    if (threadIdx.x == 0) out[(size_t)BATCH * DIN + b] = -0.5f * tot + g_LL[b];
}

// ---------------- fp16 mma.sync GEMM, cp.async 3-stage pipeline ----------------
// C[M,N] = A[M,K] @ Brows[N,K]^T, fp16 operands, fp32 accumulate.
// Warp tile 32 x WN (WN = 32 or 64).
// MODE 1: H[half] = fp16(tanh(acc+bias+tval*tvec))   MODE 2: C[float] = acc+bias
// MODE 3: no store; B cols (u,v)-interleaved; kdraw[b] += sum_k (1-h^2) u v
template <int BM, int BN, int WN, int MODE>
__global__ __launch_bounds__((BM / 32) * (BN / WN) * 32, 2)
void gemm_mma(const __half* __restrict__ A, const __half* __restrict__ B,
              void* __restrict__ Cv, int M, int N, int K,
              const void* __restrict__ biasv, void* __restrict__ auxv, float tval) {
    extern __shared__ __align__(16) char smem[];
    constexpr int THREADS = (BM / 32) * (BN / WN) * 32;
    constexpr int NT = WN / 8;          // 8x8 n-tiles per warp
    constexpr int NP = WN / 16;         // B ldmatrix.x4 per ks
    constexpr int WCOLS = BN / WN;
    constexpr int A16 = BM * 8 / THREADS;
    constexpr int B16 = BN * 8 / THREADS;
    constexpr int ABYTES = BM * 128;
    constexpr int BBYTES = BN * 128;

    float* sbias = (float*)smem;
    const uint32_t sA_u = (uint32_t)__cvta_generic_to_shared(smem + 1024);
    const uint32_t sB_u = sA_u + 3 * ABYTES;

    const int tid = threadIdx.x;
    const int lane = tid & 31;
    const int warp = tid >> 5;
    const int g = lane >> 2;
    const int tg = lane & 3;
    const int wrow = (warp / WCOLS) * 32;
    const int wcol = (warp % WCOLS) * WN;
    const int brow = blockIdx.y * BM;
    const int bcol = blockIdx.x * BN;

    if (MODE == 1) {
        const float* bias = (const float*)biasv;
        const float* tvec = (const float*)auxv;
        for (int c = tid; c < BN; c += THREADS)
            sbias[c] = bias[bcol + c] + tval * tvec[bcol + c];
    }
    if (MODE == 2) {
        const float* bias = (const float*)biasv;
        for (int c = tid; c < BN; c += THREADS) sbias[c] = bias[bcol + c];
    }

    float acc[2][NT][4];
#pragma unroll
    for (int i = 0; i < 2; i++)
#pragma unroll
        for (int j = 0; j < NT; j++)
#pragma unroll
            for (int q = 0; q < 4; q++) acc[i][j][q] = 0.f;

    const int rA_l = wrow + (lane & 15);
    const int cA_l = lane >> 4;
    const int rB_l = wcol + ((lane >> 4) * 8) + (lane & 7);
    const int cB_l = (lane >> 3) & 1;

    const int nk = K >> 6;   // 64 halves per k-tile

#define ISSUE_COPY(st, kt)                                                              \
    do {                                                                                \
        _Pragma("unroll")                                                               \
        for (int i = 0; i < A16; i++) {                                                 \
            int f = tid + i * THREADS; int r = f >> 3, seg = f & 7;                     \
            uint32_t dst = sA_u + (st) * ABYTES + r * 128 + ((seg * 16) ^ ((r & 7) * 16)); \
            CP16(dst, A + (size_t)(brow + r) * K + (kt) + seg * 8);                     \
        }                                                                               \
        _Pragma("unroll")                                                               \
        for (int i = 0; i < B16; i++) {                                                 \
            int f = tid + i * THREADS; int r = f >> 3, seg = f & 7;                     \
            uint32_t dst = sB_u + (st) * BBYTES + r * 128 + ((seg * 16) ^ ((r & 7) * 16)); \
            CP16(dst, B + (size_t)(bcol + r) * K + (kt) + seg * 8);                     \
        }                                                                               \
    } while (0)

    ISSUE_COPY(0, 0);
    CP_COMMIT();
    if (1 < nk) ISSUE_COPY(1, 64);
    CP_COMMIT();

    int t_issue = 2;
    for (int t = 0; t < nk; t++) {
        CP_WAIT1();
        __syncthreads();
        if (t_issue < nk) {
            int st = t_issue - (t_issue / 3) * 3;
            ISSUE_COPY(st, t_issue << 6);
        }
        CP_COMMIT();
        t_issue++;

        const int slot = t - (t / 3) * 3;
        const uint32_t sa = sA_u + slot * ABYTES;
        const uint32_t sb = sB_u + slot * BBYTES;
#pragma unroll
        for (int ks = 0; ks < 4; ks++) {
            uint32_t af[2][4], bf[NT][2];
#pragma unroll
            for (int mt = 0; mt < 2; mt++) {
                int r = rA_l + mt * 16;
                int ch = ks * 2 + cA_l;
                uint32_t addr = sa + r * 128 + ((ch * 16) ^ ((r & 7) * 16));
                LDMX4(af[mt][0], af[mt][1], af[mt][2], af[mt][3], addr);
            }
#pragma unroll
            for (int p = 0; p < NP; p++) {
                int r = rB_l + p * 16;
                int ch = ks * 2 + cB_l;
                uint32_t addr = sb + r * 128 + ((ch * 16) ^ ((r & 7) * 16));
                LDMX4(bf[2 * p][0], bf[2 * p][1], bf[2 * p + 1][0], bf[2 * p + 1][1], addr);
            }
#pragma unroll
            for (int mt = 0; mt < 2; mt++)
#pragma unroll
                for (int nt = 0; nt < NT; nt++)
                    MMA_F16(acc[mt][nt], af[mt], bf[nt]);
        }
    }
#undef ISSUE_COPY

    if (MODE == 3) {
        const __half* hmat = (const __half*)biasv;   // H matrix [BATCH, HID], fp16
        float* kdraw = (float*)auxv;                 // [BATCH]
        const int kbase = ((bcol + wcol) >> 1) + tg;
#pragma unroll
        for (int mt = 0; mt < 2; mt++) {
            int r0 = brow + wrow + mt * 16 + g;
            int b0 = r0 & (BATCH - 1);
            int b1 = (r0 + 8) & (BATCH - 1);
            float s0 = 0.f, s1 = 0.f;
#pragma unroll
            for (int nt = 0; nt < NT; nt++) {
                int kk = kbase + nt * 4;
                float h0 = __half2float(hmat[(size_t)b0 * HID + kk]);
                float h1 = __half2float(hmat[(size_t)b1 * HID + kk]);
                s0 += (1.f - h0 * h0) * acc[mt][nt][0] * acc[mt][nt][1];
                s1 += (1.f - h1 * h1) * acc[mt][nt][2] * acc[mt][nt][3];
            }
            s0 += __shfl_xor_sync(0xffffffffu, s0, 1);
            s0 += __shfl_xor_sync(0xffffffffu, s0, 2);
            s1 += __shfl_xor_sync(0xffffffffu, s1, 1);
            s1 += __shfl_xor_sync(0xffffffffu, s1, 2);
            if (tg == 0) {
                atomicAdd(&kdraw[b0], s0);
                atomicAdd(&kdraw[b1], s1);
            }
        }
        return;
    }

#pragma unroll
    for (int mt = 0; mt < 2; mt++) {
#pragma unroll
        for (int nt = 0; nt < NT; nt++) {
            int lc = wcol + nt * 8 + tg * 2;
            int r0 = brow + wrow + mt * 16 + g;
            float v0 = acc[mt][nt][0], v1 = acc[mt][nt][1];
            float v2 = acc[mt][nt][2], v3 = acc[mt][nt][3];
            if (MODE == 1) {
                __half* C = (__half*)Cv;
                float b0 = sbias[lc], b1 = sbias[lc + 1];
                __half2 h01 = __floats2half2_rn(tanhf(v0 + b0), tanhf(v1 + b1));
                __half2 h23 = __floats2half2_rn(tanhf(v2 + b0), tanhf(v3 + b1));
                *(__half2*)(C + (size_t)r0 * N + bcol + lc)       = h01;
                *(__half2*)(C + (size_t)(r0 + 8) * N + bcol + lc) = h23;
            } else {  // MODE 2
                float* C = (float*)Cv;
                float b0 = sbias[lc], b1 = sbias[lc + 1];
                v0 += b0; v1 += b1; v2 += b0; v3 += b1;
                *(float2*)(C + (size_t)r0 * N + bcol + lc)       = make_float2(v0, v1);
                *(float2*)(C + (size_t)(r0 + 8) * N + bcol + lc) = make_float2(v2, v3);
            }
        }
    }
}

// ---------------- host orchestration ----------------
extern "C" void kernel_launch(void* const* d_in, const int* in_sizes, int n_in,
                              void* d_out, int out_size) {
    (void)in_sizes; (void)n_in; (void)out_size;
    const float* x   = (const float*)d_in[0];
    const float* W1  = (const float*)d_in[1];
    const float* b1  = (const float*)d_in[2];
    const float* tw1 = (const float*)d_in[3];
    const float* W2  = (const float*)d_in[4];
    const float* b2  = (const float*)d_in[5];
    float* out = (float*)d_out;

    __half *pZIN, *pH, *pE, *pW1T, *pWIL, *pW2T;
    float *pK, *pKD;
    cudaGetSymbolAddress((void**)&pZIN, g_ZIN);
    cudaGetSymbolAddress((void**)&pH, g_H);
    cudaGetSymbolAddress((void**)&pE, g_E);
    cudaGetSymbolAddress((void**)&pW1T, g_W1T);
    cudaGetSymbolAddress((void**)&pWIL, g_WIL);
    cudaGetSymbolAddress((void**)&pW2T, g_W2T);
    cudaGetSymbolAddress((void**)&pK, g_K);
    cudaGetSymbolAddress((void**)&pKD, g_KD);

    // streams + fork-join events (created once; host resources only)
    static cudaStream_t sM = nullptr, sS = nullptr;
    static cudaEvent_t evRoot = nullptr, evG1 = nullptr, evS0 = nullptr,
                       evEndM = nullptr, evEndS = nullptr;
    if (!sM) {
        int loPri, hiPri;
        cudaDeviceGetStreamPriorityRange(&loPri, &hiPri);
        cudaStreamCreateWithPriority(&sM, cudaStreamNonBlocking, hiPri);
        cudaStreamCreateWithPriority(&sS, cudaStreamNonBlocking, loPri);
        cudaEventCreateWithFlags(&evRoot, cudaEventDisableTiming);
        cudaEventCreateWithFlags(&evG1, cudaEventDisableTiming);
        cudaEventCreateWithFlags(&evS0, cudaEventDisableTiming);
        cudaEventCreateWithFlags(&evEndM, cudaEventDisableTiming);
        cudaEventCreateWithFlags(&evEndS, cudaEventDisableTiming);
    }

    const int SM_BIG = 1024 + 3 * (128 + 128) * 128;  // 99328  (128x128 tiles)
    const int SM_G2  = 1024 + 3 * (64 + 64) * 128;    // 50176  (64x64 tiles)
    cudaFuncSetAttribute((const void*)gemm_mma<128, 128, 64, 1>,
                         cudaFuncAttributeMaxDynamicSharedMemorySize, SM_BIG);
    cudaFuncSetAttribute((const void*)gemm_mma<64, 64, 32, 2>,
                         cudaFuncAttributeMaxDynamicSharedMemorySize, SM_G2);
    cudaFuncSetAttribute((const void*)gemm_mma<128, 128, 64, 3>,
                         cudaFuncAttributeMaxDynamicSharedMemorySize, SM_BIG);

    // setup on the capture stream, then fork both worker streams
    init_kernel<<<(BATCH * DIN + 255) / 256, 256>>>(x);
    build_w1t<<<(HID * DIN + 255) / 256, 256>>>(W1);
    build_wil<<<(2 * HID * DIN + 255) / 256, 256>>>(W1, W2);
    build_w2t<<<(DIN * HID + 255) / 256, 256>>>(W2);
    cudaEventRecord(evRoot, 0);
    cudaStreamWaitEvent(sM, evRoot, 0);
    cudaStreamWaitEvent(sS, evRoot, 0);

    // JAX threefry, partitionable semantics
    uint32_t key0 = 0u, key1 = 1234u;

    for (int step = 0; step < NSTEPS; step++) {
        uint32_t nk0, nk1;
        uint32_t sk[4][2];
        tfry(key0, key1, 0u, 0u, nk0, nk1);
        for (int s = 0; s < 4; s++)
            tfry(key0, key1, 0u, (uint32_t)(s + 1), sk[s][0], sk[s][1]);
        key0 = nk0; key1 = nk1;

        double t0d = (double)step / 9.0, t1d = (double)(step + 1) / 9.0;
        float t0 = (float)t0d;
        float dt = (float)(t1d - t0d);
        float ts[4] = {t0, t0 + dt / 3.f, t0 + 2.f * dt / 3.f, (float)t1d};

        for (int s = 0; s < 4; s++) {
            __half* Hs = pH + (size_t)s * BATCH * HID;

            // ---- main stream (high priority): integrator chain ----
            if (s == 1)      zin_kernel<<<(BATCH * DIN + 255) / 256, 256, 0, sM>>>(dt / 3.f, 0.f, 0.f);
            else if (s == 2) zin_kernel<<<(BATCH * DIN + 255) / 256, 256, 0, sM>>>(-dt / 3.f, dt, 0.f);
            else if (s == 3) zin_kernel<<<(BATCH * DIN + 255) / 256, 256, 0, sM>>>(dt, -dt, dt);
            // (s == 0: ZIN already holds fp16(Z))

            // H-reuse guard: previous step's G3(0) must drain before H[0] rewrite
            if (s == 0 && step > 0) cudaStreamWaitEvent(sM, evS0, 0);

            // H[s] = fp16(tanh(zin @ W1 + b1 + t*tw1))   [2048x1024, K=512]
            gemm_mma<128, 128, 64, 1><<<dim3(HID / 128, BATCH / 128), 256, SM_BIG, sM>>>(
                pZIN, pW1T, Hs, BATCH, HID, DIN, b1, (void*)tw1, ts[s]);
            cudaEventRecord(evG1, sM);
            // K[s] = H[s] @ W2 + b2                      [2048x512, K=1024]
            gemm_mma<64, 64, 32, 2><<<dim3(DIN / 64, BATCH / 64), 128, SM_G2, sM>>>(
                Hs, pW2T, pK + (size_t)s * BATCH * DIN, BATCH, DIN, HID, b2, nullptr, 0.f);

            // ---- side stream (low priority): trace chain ----
            uint32_t keys_e[2][2];
            for (int i = 0; i < 2; i++) {
                uint32_t f0, f1;
                tfry(sk[s][0], sk[s][1], 0u, (uint32_t)i, f0, f1);
                tfry(f0, f1, 0u, 1u, keys_e[i][0], keys_e[i][1]);
            }
            gen_e_kernel<<<dim3(BATCH * DIN / 256, 2), 256, 0, sS>>>(
                keys_e[0][0], keys_e[0][1], keys_e[1][0], keys_e[1][1],
                pKD + (size_t)s * BATCH);
            cudaStreamWaitEvent(sS, evG1, 0);
            gemm_mma<128, 128, 64, 3><<<dim3(2 * HID / 128, 2 * BATCH / 128), 256, SM_BIG, sS>>>(
                pE, pWIL, nullptr, 2 * BATCH, 2 * HID, DIN,
                Hs, pKD + (size_t)s * BATCH, 0.f);
            if (s == 0) cudaEventRecord(evS0, sS);
        }
        // main: z update (reads only K)
        update_z<<<(BATCH * DIN + 255) / 256, 256, 0, sM>>>(dt * 0.125f);
        // side: LL update (reads only KD); next step's gen_e re-zeroes after
        update_ll<<<(BATCH + 255) / 256, 256, 0, sS>>>(dt * 0.125f);
    }
    // single final join back into the capture stream
    cudaEventRecord(evEndM, sM);
    cudaEventRecord(evEndS, sS);
    cudaStreamWaitEvent(0, evEndM, 0);
    cudaStreamWaitEvent(0, evEndS, 0);
    finalize_kernel<<<BATCH, 256>>>(out);
}